// round 8
// baseline (speedup 1.0000x reference)
#include <cuda_runtime.h>
#include <stdint.h>

#define NB 64
#define NS 512
#define ND 768
#define NROWS (NB * NS)          // 32768
#define F4_PER_ROW (ND / 4)      // 192
#define THREADS 256
#define WARPS_PER_BLOCK 8
#define NBLOCKS 592              // 4 blocks/SM x 148 SMs — single persistent wave
#define F4_PER_LANE 6            // 192 / 32

__device__ __forceinline__ uint32_t rotl32(uint32_t x, int r) {
    return (x << r) | (x >> (32 - r));
}

// JAX threefry2x32-20, key = (0, 42), partitionable path:
//   counter for element i is (hi, lo) = (0, i); 32-bit output = lane0 ^ lane1
__device__ __forceinline__ uint32_t jax_threefry_bits_partitionable(uint32_t i) {
    const uint32_t ks0 = 0u;
    const uint32_t ks1 = 42u;
    const uint32_t ks2 = 0u ^ 42u ^ 0x1BD11BDAu;

    uint32_t x0 = 0u + ks0;   // counts_hi = 0
    uint32_t x1 = i + ks1;    // counts_lo = i

#define TF_R4(r0, r1, r2, r3)                                   \
    x0 += x1; x1 = rotl32(x1, r0); x1 ^= x0;                    \
    x0 += x1; x1 = rotl32(x1, r1); x1 ^= x0;                    \
    x0 += x1; x1 = rotl32(x1, r2); x1 ^= x0;                    \
    x0 += x1; x1 = rotl32(x1, r3); x1 ^= x0;

    TF_R4(13, 15, 26, 6);  x0 += ks1; x1 += ks2 + 1u;
    TF_R4(17, 29, 16, 24); x0 += ks2; x1 += ks0 + 2u;
    TF_R4(13, 15, 26, 6);  x0 += ks0; x1 += ks1 + 3u;
    TF_R4(17, 29, 16, 24); x0 += ks1; x1 += ks2 + 4u;
    TF_R4(13, 15, 26, 6);  x0 += ks2; x1 += ks0 + 5u;
#undef TF_R4

    return x0 ^ x1;
}

// Per-row scale, identical arithmetic to all passing rounds.
__device__ __forceinline__ float row_scale(uint32_t row,
                                           const int* __restrict__ abi,
                                           const int* __restrict__ tlen,
                                           const int* __restrict__ alen) {
    const uint32_t b = row >> 9;                 // row / NS
    const uint32_t j = row & (NS - 1u);          // row % NS

    const int2 bb = *(const int2*)(abi + 2u * b);
    const int tli = tlen[b];
    const float jf  = (float)j;
    const float b0f = (float)bb.x;
    const float b1f = (float)bb.y;
    const float tlf = (float)tli;
    const float ctx = (float)(tli - alen[b]);

    // Exact IEEE divisions so fast-math can't shift the comparison boundary.
    float prox;
    if (jf < b0f)       prox = 1.0f - __fdiv_rn(b0f - jf, ctx);
    else if (jf <= b1f) prox = __fdiv_rn(1.0f, ctx);
    else                prox = 1.0f - __fdiv_rn(jf - b1f, ctx);
    if (!(jf < tlf)) prox = 0.0f;
    prox = fminf(fmaxf(prox, 0.0f), 1.0f);

    const uint32_t bits = jax_threefry_bits_partitionable(row);
    const float u = __uint_as_float((bits >> 9) | 0x3f800000u) - 1.0f;
    const float mask = (u < prox) ? 1.0f : 0.0f;

    return __fdiv_rn(mask, prox + 1e-5f);
}

__global__ __launch_bounds__(THREADS)
void position_dropout_kernel(const float4* __restrict__ x,
                             const int* __restrict__ abi,   // [B,2]
                             const int* __restrict__ tlen,  // [B]
                             const int* __restrict__ alen,  // [B]
                             float4* __restrict__ out) {
    const uint32_t t = threadIdx.x;
    const uint32_t lane = t & 31u;
    const uint32_t gw = blockIdx.x * WARPS_PER_BLOCK + (t >> 5);  // global warp id
    const uint32_t W = NBLOCKS * WARPS_PER_BLOCK;                 // 4736 warps

    uint32_t row = gw;
    if (row >= NROWS) return;

    // Prologue: loads for the first row.
    uint32_t base = row * F4_PER_ROW + lane;
    float4 cur[F4_PER_LANE];
#pragma unroll
    for (int k = 0; k < F4_PER_LANE; k++)
        cur[k] = x[base + 32u * k];

    // Persistent pipelined loop: issue next row's loads BEFORE computing the
    // current row's scale + stores, so this warp always has loads in flight —
    // no CTA teardown/dispatch gaps in the load stream.
    while (true) {
        const uint32_t nrow = row + W;
        const bool more = (nrow < NROWS);

        float4 nxt[F4_PER_LANE];
        const uint32_t nbase = nrow * F4_PER_ROW + lane;
        if (more) {
#pragma unroll
            for (int k = 0; k < F4_PER_LANE; k++)
                nxt[k] = x[nbase + 32u * k];
        }

        float sc = 0.0f;
        if (lane == 0)
            sc = row_scale(row, abi, tlen, alen);
        sc = __shfl_sync(0xffffffffu, sc, 0);

#pragma unroll
        for (int k = 0; k < F4_PER_LANE; k++) {
            float4 w = cur[k];
            w.x *= sc; w.y *= sc; w.z *= sc; w.w *= sc;
            out[base + 32u * k] = w;
        }

        if (!more) break;
#pragma unroll
        for (int k = 0; k < F4_PER_LANE; k++)
            cur[k] = nxt[k];
        row = nrow;
        base = nbase;
    }
}

extern "C" void kernel_launch(void* const* d_in, const int* in_sizes, int n_in,
                              void* d_out, int out_size) {
    const float4* x = (const float4*)d_in[0];
    const int* abi  = (const int*)d_in[1];
    const int* tlen = (const int*)d_in[2];
    const int* alen = (const int*)d_in[3];
    float4* out = (float4*)d_out;

    position_dropout_kernel<<<NBLOCKS, THREADS>>>(x, abi, tlen, alen, out);
}